// round 16
// baseline (speedup 1.0000x reference)
#include <cuda_runtime.h>
#include <cuda_fp16.h>
#include <cstdint>

#define BATCH    8192
#define HID      128
#define GATES    512
#define LOOKBACK 48
#define HORIZON  12
#define TSTEPS   60
#define DIN      8
#define STATE    (BATCH*HID)
#define KROW0    160          // 8 x + 24 zero pad + 128 h (halves)
#define KROW1    256
#define NTHR     512

// ---- device globals ----
__device__ __half g_WB0[GATES*KROW0];   // n-major [n][k], n = unit*4+gate
__device__ __half g_WB1[GATES*KROW1];
__device__ float  g_b0 [GATES];
__device__ float  g_b1 [GATES];
__device__ __half g_h0 [2*STATE];
__device__ __half g_h1 [2*STATE];
__device__ float  g_c0 [STATE];          // CTA-blocked: [slot][tid][16]
__device__ float  g_c1 [STATE];
__device__ float  g_fcp[2*BATCH];

// ---- smem (bytes): hdr 2048 | A @2048 | B @69632 ----
#define OA     2048
#define OB     69632
#define SM_HB  35328
#define SMEM_TOTAL 204800

// ---------------- helpers ----------------
__device__ __forceinline__ uint32_t smem_u32(const void* p){
    uint32_t a;
    asm("{ .reg .u64 t; cvta.to.shared.u64 t, %1; cvt.u32.u64 %0, t; }" : "=r"(a) : "l"(p));
    return a;
}
__device__ __forceinline__ void cpa16(uint32_t dst, const void* src){
    asm volatile("cp.async.cg.shared.global [%0], [%1], 16;" :: "r"(dst), "l"(src));
}
#define CP_COMMIT() asm volatile("cp.async.commit_group;" ::: "memory")
#define CP_WAIT0()  asm volatile("cp.async.wait_group 0;" ::: "memory")
__device__ __forceinline__ void pdl_wait(){
    asm volatile("griddepcontrol.wait;" ::: "memory");
}
__device__ __forceinline__ void pdl_trigger(){
    asm volatile("griddepcontrol.launch_dependents;");
}
__device__ __forceinline__ void ldsm4(uint32_t* r, uint32_t addr){
    asm volatile("ldmatrix.sync.aligned.m8n8.x4.shared.b16 {%0,%1,%2,%3}, [%4];"
        : "=r"(r[0]), "=r"(r[1]), "=r"(r[2]), "=r"(r[3]) : "r"(addr));
}
__device__ __forceinline__ void mma16(float* d, const uint32_t* a, const uint32_t* b){
    asm volatile("mma.sync.aligned.m16n8k16.row.col.f32.f16.f16.f32 "
        "{%0,%1,%2,%3}, {%4,%5,%6,%7}, {%8,%9}, {%0,%1,%2,%3};"
        : "+f"(d[0]), "+f"(d[1]), "+f"(d[2]), "+f"(d[3])
        : "r"(a[0]), "r"(a[1]), "r"(a[2]), "r"(a[3]), "r"(b[0]), "r"(b[1]));
}
__device__ __forceinline__ float tanh_f(float x){
    float y; asm("tanh.approx.f32 %0, %1;" : "=f"(y) : "f"(x));
    return y;
}
__device__ __forceinline__ float sigm_f(float x){
    float y; asm("tanh.approx.f32 %0, %1;" : "=f"(y) : "f"(0.5f*x));
    return fmaf(0.5f, y, 0.5f);
}

// ---------------- weight repack (n-major fp16) + state zero ----------------
__global__ void prep_kernel(const float* __restrict__ Wih0, const float* __restrict__ Whh0,
                            const float* __restrict__ bih0, const float* __restrict__ bhh0,
                            const float* __restrict__ Wih1, const float* __restrict__ Whh1,
                            const float* __restrict__ bih1, const float* __restrict__ bhh1)
{
    const int NW0 = GATES*KROW0, NW1 = GATES*KROW1;
    const int total = NW0 + NW1 + 2*GATES + 4*STATE;
    for (int idx = blockIdx.x*blockDim.x + threadIdx.x; idx < total;
         idx += gridDim.x*blockDim.x) {
        int i = idx;
        if (i < NW0) { int n = i/KROW0, k = i%KROW0; int row = (n&3)*HID + (n>>2);
            float v = 0.f;
            if (k < DIN)       v = Wih0[row*DIN + k];
            else if (k >= 32)  v = Whh0[row*HID + (k-32)];
            g_WB0[i] = __float2half_rn(v); continue; }
        i -= NW0;
        if (i < NW1) { int n = i>>8, k = i&255; int row = (n&3)*HID + (n>>2);
            float v = (k < HID) ? Wih1[row*HID + k] : Whh1[row*HID + (k-HID)];
            g_WB1[i] = __float2half_rn(v); continue; }
        i -= NW1;
        if (i < GATES) { int row = (i&3)*HID + (i>>2); g_b0[i] = bih0[row]+bhh0[row]; continue; }
        i -= GATES;
        if (i < GATES) { int row = (i&3)*HID + (i>>2); g_b1[i] = bih1[row]+bhh1[row]; continue; }
        i -= GATES;
        if (i < STATE) { g_h0[i] = __ushort_as_half((unsigned short)0); continue; }
        i -= STATE;
        if (i < STATE) { g_h1[i] = __ushort_as_half((unsigned short)0); continue; }
        i -= STATE;
        if (i < STATE) { g_c0[i] = 0.f; continue; }     // blocked layout, all zero
        i -= STATE;
        g_c1[i] = 0.f;
    }
}

// ---------------- fused LSTM cell: PDL + ldmatrix + register-resident c ----------------
template<int NCH, int ASTH, int BSTH, bool ISL0>
__global__ __launch_bounds__(NTHR, 1) void lstm_cell(
    const float* __restrict__ xf, int sx,
    const __half* __restrict__ asrc0, const __half* __restrict__ asrc1,
    const __half* __restrict__ WB,
    const float* __restrict__ bias,
    float* __restrict__ cglob, __half* __restrict__ hout,
    const float* __restrict__ Wfc, const float* __restrict__ bfc,
    float* __restrict__ fcp, float* __restrict__ out,
    int use_bg, int outcol, int dofc)
{
    constexpr int KROW = NCH*32;
    extern __shared__ __align__(16) char smem[];
    const int tid = threadIdx.x, lane = tid & 31, wid = tid >> 5;
    const int m0 = blockIdx.x * 128, n0 = blockIdx.y * 256, slice = blockIdx.y;
    const int wm0 = (wid >> 3) * 64, wn0 = (wid & 7) * 32;
    const int g = lane >> 2, tq = lane & 3;
    const uint32_t sbase = smem_u32(smem);
    float* bsm  = (float*)smem;
    float* wfcs = (float*)(smem + 1024);
    float* predS= (float*)(smem + 1536);

    // ======== PRE-WAIT: dependency depth >= 2 (safe via trigger transitivity) ========
    float* cb = cglob + (((size_t)blockIdx.x*2 + blockIdx.y)*NTHR + tid)*16;
    float creg[16];
    {
        const float4* cp4 = (const float4*)cb;
        #pragma unroll
        for (int i = 0; i < 4; i++) *(float4*)&creg[i*4] = __ldg(cp4 + i);
    }
    float xreg[8];
    if (ISL0 && (tid & 3) == 0) {          // x row (pure input)
        int m = tid >> 2;
        *(float4*)&xreg[0] = __ldg((const float4*)(xf + (size_t)(m0+m)*sx));
        *(float4*)&xreg[4] = __ldg((const float4*)(xf + (size_t)(m0+m)*sx + 4));
    }
    {
        const int brow = tid >> 1, bq = tid & 1;        // B: 256 rows, 2 thr/row
        #pragma unroll
        for (int j = 0; j < NCH; j++) {
            cpa16(sbase + OB + (uint32_t)(brow*(BSTH*2) + j*64 + bq*32),
                  (const char*)WB + ((size_t)(n0+brow)*KROW + j*32)*2 + bq*32);
            cpa16(sbase + OB + (uint32_t)(brow*(BSTH*2) + j*64 + bq*32 + 16),
                  (const char*)WB + ((size_t)(n0+brow)*KROW + j*32)*2 + bq*32 + 16);
        }
        const int arow = tid >> 2, aq = tid & 3;        // A: 128 rows, 4 thr/row
        if (ISL0) {
            #pragma unroll
            for (int j = 1; j < NCH; j++)               // h0_prev: 2 launches back
                cpa16(sbase + OA + (uint32_t)(arow*(ASTH*2) + j*64 + aq*16),
                      (const char*)(asrc0 + (size_t)(m0+arow)*HID + (j-1)*32) + aq*16);
            if ((tid & 3) != 0) {                       // chunk0 zero pad
                __half* As0 = (__half*)(smem + OA);
                int m = tid >> 2, part = tid & 3;
                uint4 z = {0,0,0,0};
                *(uint4*)&As0[m*ASTH + part*8] = z;
            }
        } else {
            #pragma unroll
            for (int j = 4; j < 8; j++)                 // h1_prev: 2 launches back
                cpa16(sbase + OA + (uint32_t)(arow*(ASTH*2) + j*64 + aq*16),
                      (const char*)(asrc1 + (size_t)(m0+arow)*HID + (j-4)*32) + aq*16);
        }
    }
    if (tid < 256) bsm[tid] = bias[n0 + tid];           // static
    if (tid < 128) wfcs[tid] = Wfc[tid];                // static

    // ======== WAIT on immediate predecessor, then dependent loads ========
    pdl_wait();

    if (ISL0) {
        if (use_bg) {
            if (tid < 128) {
                float pv = bfc[0] + fcp[m0 + tid] + fcp[BATCH + m0 + tid];
                predS[tid] = pv;
                if (n0 == 0) out[(size_t)(m0 + tid)*HORIZON + outcol] = pv;
            }
            __syncthreads();    // predS visible to chunk0 writers
        }
        if ((tid & 3) == 0) {   // chunk0 halves 0..7: x (+BG) -> f16 STS
            __half* As0 = (__half*)(smem + OA);
            int m = tid >> 2;
            if (use_bg) xreg[0] = predS[m];
            __half hv[8];
            #pragma unroll
            for (int c = 0; c < 8; c++) hv[c] = __float2half_rn(xreg[c]);
            *(uint4*)&As0[m*ASTH] = *(uint4*)hv;
        }
    } else {
        const int arow = tid >> 2, aq = tid & 3;
        #pragma unroll
        for (int j = 0; j < 4; j++)                     // h0 current: immediate dep
            cpa16(sbase + OA + (uint32_t)(arow*(ASTH*2) + j*64 + aq*16),
                  (const char*)(asrc0 + (size_t)(m0+arow)*HID + j*32) + aq*16);
    }
    CP_COMMIT();

    float acc[4][4][4];
    #pragma unroll
    for (int a = 0; a < 4; a++)
        #pragma unroll
        for (int b = 0; b < 4; b++)
            #pragma unroll
            for (int d = 0; d < 4; d++) acc[a][b][d] = 0.f;

    // ======== single wait + single barrier, then ldmatrix mainloop ========
    CP_WAIT0();
    __syncthreads();
    {
        const int t4 = lane >> 3;
        const uint32_t a_base = sbase + OA
            + (uint32_t)(((wm0 + (t4&1)*8 + (lane&7))*ASTH + (t4>>1)*8)*2);
        const uint32_t b_base = sbase + OB
            + (uint32_t)(((wn0 + (t4>>1)*8 + (lane&7))*BSTH + (t4&1)*8)*2);
        #pragma unroll
        for (int j = 0; j < NCH; j++) {
            #pragma unroll
            for (int s = 0; s < 2; s++) {
                const uint32_t koff = (uint32_t)((j*32 + s*16)*2);
                uint32_t af[4][4];
                #pragma unroll
                for (int mi = 0; mi < 4; mi++)
                    ldsm4(af[mi], a_base + (uint32_t)(mi*16*ASTH*2) + koff);
                uint32_t bfr[2][4];
                #pragma unroll
                for (int nh = 0; nh < 2; nh++)
                    ldsm4(bfr[nh], b_base + (uint32_t)(nh*16*BSTH*2) + koff);
                #pragma unroll
                for (int mi = 0; mi < 4; mi++)
                    #pragma unroll
                    for (int nj = 0; nj < 4; nj++)
                        mma16(acc[mi][nj], af[mi], &bfr[nj>>1][(nj&1)*2]);
            }
        }
    }
    __syncthreads();   // all warps done with A before hbuf aliases it

    // ======== epilogue: gates in registers, c stays in registers ========
    __half* hbuf = (__half*)(smem + SM_HB);   // 128 x 66 half
    const int ub = n0 >> 2;
    const int odd = lane & 1;
    #pragma unroll
    for (int mi = 0; mi < 4; mi++) {
        #pragma unroll
        for (int nj = 0; nj < 4; nj++) {
            int nl = wn0 + nj*8 + 2*tq;
            float v0 = acc[mi][nj][0] + bsm[nl];
            float v1 = acc[mi][nj][1] + bsm[nl+1];
            float v2 = acc[mi][nj][2] + bsm[nl];
            float v3 = acc[mi][nj][3] + bsm[nl+1];
            float x = __shfl_xor_sync(0xffffffffu, odd ? v0 : v2, 1);
            float y = __shfl_xor_sync(0xffffffffu, odd ? v1 : v3, 1);
            float gi = odd ? x  : v0;
            float gf = odd ? y  : v1;
            float gg = odd ? v2 : x;
            float go = odd ? v3 : y;
            int u   = nl >> 2;
            int mlr = wm0 + mi*16 + g + (odd ? 8 : 0);
            float cold = creg[mi*4 + nj];
            float cn = sigm_f(gf)*cold + sigm_f(gi)*tanh_f(gg);
            creg[mi*4 + nj] = cn;
            hbuf[mlr*66 + u] = __float2half_rn(sigm_f(go)*tanh_f(cn));
        }
    }
    {   // c writeback: 4 coalesced STG.128 (blocked layout)
        float4* cp4 = (float4*)cb;
        #pragma unroll
        for (int i = 0; i < 4; i++) cp4[i] = *(float4*)&creg[i*4];
    }
    __syncthreads();
    if (dofc && tid < 256) {
        int row = tid >> 1, hf = tid & 1;
        float s = 0.f;
        #pragma unroll
        for (int jj = 0; jj < 32; jj++) {
            int u = hf*32 + jj;
            s += __half2float(hbuf[row*66 + u]) * wfcs[ub + u];
        }
        s += __shfl_xor_sync(0xffffffffu, s, 1);
        if (!hf) fcp[slice*BATCH + m0 + row] = s;
    }
    const uint32_t* hw = (const uint32_t*)hbuf;
    #pragma unroll
    for (int i = 0; i < 2; i++) {             // h writeback (half), coalesced
        int idx = tid + i*NTHR;
        int m = idx >> 3, q = idx & 7;
        uint4 w;
        int bw = m*33 + q*4;
        w.x = hw[bw]; w.y = hw[bw+1]; w.z = hw[bw+2]; w.w = hw[bw+3];
        *(uint4*)&hout[(size_t)(m0+m)*HID + ub + q*8] = w;
    }
    pdl_trigger();
}

// ---------------- tail: last horizon column ----------------
__global__ void fc_tail(const float* __restrict__ fcp, const float* __restrict__ bfc,
                        float* __restrict__ out)
{
    int row = blockIdx.x*128 + threadIdx.x;
    out[(size_t)row*HORIZON + (HORIZON-1)] = bfc[0] + fcp[row] + fcp[BATCH + row];
}

// ---------------- launch ----------------
extern "C" void kernel_launch(void* const* d_in, const int* in_sizes, int n_in,
                              void* d_out, int out_size)
{
    const float* inputs = (const float*)d_in[0];
    const float* Wih0 = (const float*)d_in[1];
    const float* Whh0 = (const float*)d_in[2];
    const float* bih0 = (const float*)d_in[3];
    const float* bhh0 = (const float*)d_in[4];
    const float* Wih1 = (const float*)d_in[5];
    const float* Whh1 = (const float*)d_in[6];
    const float* bih1 = (const float*)d_in[7];
    const float* bhh1 = (const float*)d_in[8];
    const float* Wfc  = (const float*)d_in[9];
    const float* bfc  = (const float*)d_in[10];
    float* out = (float*)d_out;

    __half *pWB0,*pWB1,*ph0,*ph1;
    float *pb0,*pb1,*pc0,*pc1,*pfcp;
    cudaGetSymbolAddress((void**)&pWB0, g_WB0);
    cudaGetSymbolAddress((void**)&pWB1, g_WB1);
    cudaGetSymbolAddress((void**)&pb0 , g_b0 );
    cudaGetSymbolAddress((void**)&pb1 , g_b1 );
    cudaGetSymbolAddress((void**)&ph0 , g_h0 );
    cudaGetSymbolAddress((void**)&ph1 , g_h1 );
    cudaGetSymbolAddress((void**)&pc0 , g_c0 );
    cudaGetSymbolAddress((void**)&pc1 , g_c1 );
    cudaGetSymbolAddress((void**)&pfcp, g_fcp);

    auto k0 = lstm_cell<KROW0/32, KROW0+8, KROW0+8, true >;
    auto k1 = lstm_cell<KROW1/32, KROW1+8, KROW1+8, false>;
    cudaFuncSetAttribute(k0, cudaFuncAttributeMaxDynamicSharedMemorySize, SMEM_TOTAL);
    cudaFuncSetAttribute(k1, cudaFuncAttributeMaxDynamicSharedMemorySize, SMEM_TOTAL);

    prep_kernel<<<2048, 256>>>(Wih0, Whh0, bih0, bhh0, Wih1, Whh1, bih1, bhh1);

    dim3 grid(BATCH/128, 2);
    cudaLaunchConfig_t cfg = {};
    cfg.gridDim = grid;
    cfg.blockDim = dim3(NTHR, 1, 1);
    cfg.dynamicSmemBytes = SMEM_TOTAL;
    cfg.stream = 0;
    cudaLaunchAttribute attrs[1];
    attrs[0].id = cudaLaunchAttributeProgrammaticStreamSerialization;
    attrs[0].val.programmaticStreamSerializationAllowed = 1;
    cfg.attrs = attrs;
    cfg.numAttrs = 1;

    for (int t = 0; t < TSTEPS; t++) {
        int rp = t & 1, wp = 1 - rp;
        int use_bg = (t > LOOKBACK) ? 1 : 0;
        cudaLaunchKernelEx(&cfg, k0,
            (const float*)(inputs + t*DIN), (int)(TSTEPS*DIN),
            (const __half*)(ph0 + rp*STATE), (const __half*)(ph0 + rp*STATE),
            (const __half*)pWB0, (const float*)pb0,
            pc0, (__half*)(ph0 + wp*STATE),
            Wfc, bfc, pfcp, out,
            use_bg, t - 1 - LOOKBACK, 0);
        cudaLaunchKernelEx(&cfg, k1,
            (const float*)nullptr, 0,
            (const __half*)(ph0 + wp*STATE), (const __half*)(ph1 + rp*STATE),
            (const __half*)pWB1, (const float*)pb1,
            pc1, (__half*)(ph1 + wp*STATE),
            Wfc, bfc, pfcp, out,
            0, 0, (t >= LOOKBACK) ? 1 : 0);
    }
    fc_tail<<<BATCH/128, 128>>>(pfcp, bfc, out);
}

// round 17
// speedup vs baseline: 1.0620x; 1.0620x over previous
#include <cuda_runtime.h>
#include <cuda_fp16.h>
#include <cstdint>

#define BATCH    8192
#define HID      128
#define GATES    512
#define LOOKBACK 48
#define HORIZON  12
#define TSTEPS   60
#define DIN      8
#define STATE    (BATCH*HID)
#define KROW0    160          // NEW layout: h(0..127) | x(128..135) | pad(136..159)
#define KROW1    256
#define NTHR     512

// ---- device globals ----
__device__ __half g_WB0[GATES*KROW0];   // n-major [n][k]
__device__ __half g_WB1[GATES*KROW1];
__device__ float  g_b0 [GATES];
__device__ float  g_b1 [GATES];
__device__ __half g_h0 [2*STATE];
__device__ __half g_h1 [2*STATE];
__device__ float  g_c0 [STATE];          // CTA-blocked [slot][tid][16]
__device__ float  g_c1 [STATE];
__device__ float  g_fcp[2*BATCH];

// ---- smem layouts ----
// standalone: hdr 2048 | A @2048 | B @69632 ; hbuf @35328 aliases A (dead)
#define OA     2048
#define OB     69632
#define SM_HB  35328
#define SMEM_STD 204800
// merged: bias1 @0 | bias0 @1024 | A @2048 (128x528B) | B @69632 (256x528B) | HB2 @204800
#define OHB2   204800
#define SMEM_MRG 221696
#define MASTB  528            // merged A row stride bytes (264 halves)
#define MBSTB  528

// ---------------- helpers ----------------
__device__ __forceinline__ uint32_t smem_u32(const void* p){
    uint32_t a;
    asm("{ .reg .u64 t; cvta.to.shared.u64 t, %1; cvt.u32.u64 %0, t; }" : "=r"(a) : "l"(p));
    return a;
}
__device__ __forceinline__ void cpa16(uint32_t dst, const void* src){
    asm volatile("cp.async.cg.shared.global [%0], [%1], 16;" :: "r"(dst), "l"(src));
}
#define CP_COMMIT() asm volatile("cp.async.commit_group;" ::: "memory")
#define CP_WAIT0()  asm volatile("cp.async.wait_group 0;" ::: "memory")
__device__ __forceinline__ void pdl_wait(){
    asm volatile("griddepcontrol.wait;" ::: "memory");
}
__device__ __forceinline__ void pdl_trigger(){
    asm volatile("griddepcontrol.launch_dependents;");
}
__device__ __forceinline__ void ldsm4(uint32_t* r, uint32_t addr){
    asm volatile("ldmatrix.sync.aligned.m8n8.x4.shared.b16 {%0,%1,%2,%3}, [%4];"
        : "=r"(r[0]), "=r"(r[1]), "=r"(r[2]), "=r"(r[3]) : "r"(addr));
}
__device__ __forceinline__ void mma16(float* d, const uint32_t* a, const uint32_t* b){
    asm volatile("mma.sync.aligned.m16n8k16.row.col.f32.f16.f16.f32 "
        "{%0,%1,%2,%3}, {%4,%5,%6,%7}, {%8,%9}, {%0,%1,%2,%3};"
        : "+f"(d[0]), "+f"(d[1]), "+f"(d[2]), "+f"(d[3])
        : "r"(a[0]), "r"(a[1]), "r"(a[2]), "r"(a[3]), "r"(b[0]), "r"(b[1]));
}
__device__ __forceinline__ float tanh_f(float x){
    float y; asm("tanh.approx.f32 %0, %1;" : "=f"(y) : "f"(x));
    return y;
}
__device__ __forceinline__ float sigm_f(float x){
    float y; asm("tanh.approx.f32 %0, %1;" : "=f"(y) : "f"(0.5f*x));
    return fmaf(0.5f, y, 0.5f);
}

template<int NCH>
__device__ __forceinline__ void gemm_loop(uint32_t a_base, uint32_t b_base,
                                          int astB, int bstB, float (&acc)[4][4][4]){
    #pragma unroll
    for (int j = 0; j < NCH; j++){
        #pragma unroll
        for (int s = 0; s < 2; s++){
            const uint32_t koff = (uint32_t)((j*32 + s*16)*2);
            uint32_t af[4][4];
            #pragma unroll
            for (int mi = 0; mi < 4; mi++)
                ldsm4(af[mi], a_base + (uint32_t)(mi*16*astB) + koff);
            uint32_t bfr[2][4];
            #pragma unroll
            for (int nh = 0; nh < 2; nh++)
                ldsm4(bfr[nh], b_base + (uint32_t)(nh*16*bstB) + koff);
            #pragma unroll
            for (int mi = 0; mi < 4; mi++)
                #pragma unroll
                for (int nj = 0; nj < 4; nj++)
                    mma16(acc[mi][nj], af[mi], &bfr[nj>>1][(nj&1)*2]);
        }
    }
}

__device__ __forceinline__ void lstm_epilogue(
    float (&acc)[4][4][4], float (&creg)[16],
    const float* bsm, __half* hbuf, int hst,
    int wm0, int wn0, int g, int tq, int lane)
{
    const int odd = lane & 1;
    #pragma unroll
    for (int mi = 0; mi < 4; mi++)
        #pragma unroll
        for (int nj = 0; nj < 4; nj++){
            int nl = wn0 + nj*8 + 2*tq;
            float v0 = acc[mi][nj][0] + bsm[nl];
            float v1 = acc[mi][nj][1] + bsm[nl+1];
            float v2 = acc[mi][nj][2] + bsm[nl];
            float v3 = acc[mi][nj][3] + bsm[nl+1];
            float x = __shfl_xor_sync(0xffffffffu, odd ? v0 : v2, 1);
            float y = __shfl_xor_sync(0xffffffffu, odd ? v1 : v3, 1);
            float gi = odd ? x  : v0;
            float gf = odd ? y  : v1;
            float gg = odd ? v2 : x;
            float go = odd ? v3 : y;
            int u   = nl >> 2;
            int mlr = wm0 + mi*16 + g + (odd ? 8 : 0);
            float cold = creg[mi*4 + nj];
            float cn = sigm_f(gf)*cold + sigm_f(gi)*tanh_f(gg);
            creg[mi*4 + nj] = cn;
            hbuf[mlr*hst + u] = __float2half_rn(sigm_f(go)*tanh_f(cn));
        }
}

// ---------------- weight repack + state zero ----------------
__global__ void prep_kernel(const float* __restrict__ Wih0, const float* __restrict__ Whh0,
                            const float* __restrict__ bih0, const float* __restrict__ bhh0,
                            const float* __restrict__ Wih1, const float* __restrict__ Whh1,
                            const float* __restrict__ bih1, const float* __restrict__ bhh1)
{
    const int NW0 = GATES*KROW0, NW1 = GATES*KROW1;
    const int total = NW0 + NW1 + 2*GATES + 4*STATE;
    for (int idx = blockIdx.x*blockDim.x + threadIdx.x; idx < total;
         idx += gridDim.x*blockDim.x) {
        int i = idx;
        if (i < NW0) { int n = i/KROW0, k = i%KROW0; int row = (n&3)*HID + (n>>2);
            float v = 0.f;
            if (k < HID)            v = Whh0[row*HID + k];
            else if (k < HID+DIN)   v = Wih0[row*DIN + (k-HID)];
            g_WB0[i] = __float2half_rn(v); continue; }
        i -= NW0;
        if (i < NW1) { int n = i>>8, k = i&255; int row = (n&3)*HID + (n>>2);
            float v = (k < HID) ? Wih1[row*HID + k] : Whh1[row*HID + (k-HID)];
            g_WB1[i] = __float2half_rn(v); continue; }
        i -= NW1;
        if (i < GATES) { int row = (i&3)*HID + (i>>2); g_b0[i] = bih0[row]+bhh0[row]; continue; }
        i -= GATES;
        if (i < GATES) { int row = (i&3)*HID + (i>>2); g_b1[i] = bih1[row]+bhh1[row]; continue; }
        i -= GATES;
        if (i < STATE) { g_h0[i] = __ushort_as_half((unsigned short)0); continue; }
        i -= STATE;
        if (i < STATE) { g_h1[i] = __ushort_as_half((unsigned short)0); continue; }
        i -= STATE;
        if (i < STATE) { g_c0[i] = 0.f; continue; }
        i -= STATE;
        g_c1[i] = 0.f;
    }
}

// ---------------- standalone cell (k0 with new layout; k1 unchanged) ----------------
template<int NCH, int ASTH, int BSTH, bool ISL0>
__global__ __launch_bounds__(NTHR, 1) void lstm_cell(
    const float* __restrict__ xf, int sx,
    const __half* __restrict__ asrc0, const __half* __restrict__ asrc1,
    const __half* __restrict__ WB,
    const float* __restrict__ bias,
    float* __restrict__ cglob, __half* __restrict__ hout,
    const float* __restrict__ Wfc, const float* __restrict__ bfc,
    float* __restrict__ fcp, float* __restrict__ out,
    int use_bg, int outcol, int dofc)
{
    constexpr int KROW = NCH*32;
    extern __shared__ __align__(16) char smem[];
    const int tid = threadIdx.x, lane = tid & 31, wid = tid >> 5;
    const int m0 = blockIdx.x * 128, n0 = blockIdx.y * 256, slice = blockIdx.y;
    const int wm0 = (wid >> 3) * 64, wn0 = (wid & 7) * 32;
    const int g = lane >> 2, tq = lane & 3;
    const uint32_t sbase = smem_u32(smem);
    float* bsm  = (float*)smem;
    float* wfcs = (float*)(smem + 1024);
    float* predS= (float*)(smem + 1536);

    // ---- pre-wait (2-back safe) ----
    float* cb = cglob + (((size_t)blockIdx.x*2 + blockIdx.y)*NTHR + tid)*16;
    float creg[16];
    {
        const float4* cp4 = (const float4*)cb;
        #pragma unroll
        for (int i = 0; i < 4; i++) *(float4*)&creg[i*4] = __ldg(cp4 + i);
    }
    float xreg[8];
    if (ISL0 && (tid & 3) == 0) {
        int m = tid >> 2;
        *(float4*)&xreg[0] = __ldg((const float4*)(xf + (size_t)(m0+m)*sx));
        *(float4*)&xreg[4] = __ldg((const float4*)(xf + (size_t)(m0+m)*sx + 4));
    }
    {
        const int brow = tid >> 1, bq = tid & 1;
        #pragma unroll
        for (int j = 0; j < NCH; j++) {
            cpa16(sbase + OB + (uint32_t)(brow*(BSTH*2) + j*64 + bq*32),
                  (const char*)WB + ((size_t)(n0+brow)*KROW + j*32)*2 + bq*32);
            cpa16(sbase + OB + (uint32_t)(brow*(BSTH*2) + j*64 + bq*32 + 16),
                  (const char*)WB + ((size_t)(n0+brow)*KROW + j*32)*2 + bq*32 + 16);
        }
        const int arow = tid >> 2, aq = tid & 3;
        if (ISL0) {
            #pragma unroll
            for (int j = 0; j < 4; j++)                 // h0_prev at k 0..127 (2-back)
                cpa16(sbase + OA + (uint32_t)(arow*(ASTH*2) + j*64 + aq*16),
                      (const char*)(asrc0 + (size_t)(m0+arow)*HID + j*32) + aq*16);
            if ((tid & 3) != 0) {                       // pad halves 136..159
                __half* As0 = (__half*)(smem + OA);
                int m = tid >> 2, part = tid & 3;
                uint4 z = {0,0,0,0};
                *(uint4*)&As0[m*ASTH + 128 + part*8] = z;
            }
        } else {
            #pragma unroll
            for (int j = 4; j < 8; j++)                 // h1_prev (2-back)
                cpa16(sbase + OA + (uint32_t)(arow*(ASTH*2) + j*64 + aq*16),
                      (const char*)(asrc1 + (size_t)(m0+arow)*HID + (j-4)*32) + aq*16);
        }
    }
    if (tid < 256) bsm[tid] = bias[n0 + tid];
    if (tid < 128) wfcs[tid] = Wfc[tid];

    // ---- wait, then immediate-dep loads ----
    pdl_wait();

    if (ISL0) {
        if (use_bg) {
            if (tid < 128) {
                float pv = bfc[0] + fcp[m0 + tid] + fcp[BATCH + m0 + tid];
                predS[tid] = pv;
                if (n0 == 0) out[(size_t)(m0 + tid)*HORIZON + outcol] = pv;
            }
            __syncthreads();
        }
        if ((tid & 3) == 0) {   // x at halves 128..135
            __half* As0 = (__half*)(smem + OA);
            int m = tid >> 2;
            if (use_bg) xreg[0] = predS[m];
            __half hv[8];
            #pragma unroll
            for (int c = 0; c < 8; c++) hv[c] = __float2half_rn(xreg[c]);
            *(uint4*)&As0[m*ASTH + 128] = *(uint4*)hv;
        }
    } else {
        const int arow = tid >> 2, aq = tid & 3;
        #pragma unroll
        for (int j = 0; j < 4; j++)                     // h0 current (immediate)
            cpa16(sbase + OA + (uint32_t)(arow*(ASTH*2) + j*64 + aq*16),
                  (const char*)(asrc0 + (size_t)(m0+arow)*HID + j*32) + aq*16);
    }
    CP_COMMIT();

    float acc[4][4][4];
    #pragma unroll
    for (int a = 0; a < 4; a++)
        #pragma unroll
        for (int b = 0; b < 4; b++)
            #pragma unroll
            for (int d = 0; d < 4; d++) acc[a][b][d] = 0.f;

    CP_WAIT0();
    __syncthreads();
    {
        const int t4 = lane >> 3;
        const uint32_t a_base = sbase + OA
            + (uint32_t)(((wm0 + (t4&1)*8 + (lane&7))*ASTH + (t4>>1)*8)*2);
        const uint32_t b_base = sbase + OB
            + (uint32_t)(((wn0 + (t4>>1)*8 + (lane&7))*BSTH + (t4&1)*8)*2);
        gemm_loop<NCH>(a_base, b_base, ASTH*2, BSTH*2, acc);
    }
    __syncthreads();

    __half* hbuf = (__half*)(smem + SM_HB);
    const int ub = n0 >> 2;
    lstm_epilogue(acc, creg, bsm, hbuf, 66, wm0, wn0, g, tq, lane);
    {
        float4* cp4 = (float4*)cb;
        #pragma unroll
        for (int i = 0; i < 4; i++) cp4[i] = *(float4*)&creg[i*4];
    }
    __syncthreads();
    if (dofc && tid < 256) {
        int row = tid >> 1, hf = tid & 1;
        float s = 0.f;
        #pragma unroll
        for (int jj = 0; jj < 32; jj++) {
            int u = hf*32 + jj;
            s += __half2float(hbuf[row*66 + u]) * wfcs[ub + u];
        }
        s += __shfl_xor_sync(0xffffffffu, s, 1);
        if (!hf) fcp[slice*BATCH + m0 + row] = s;
    }
    const uint32_t* hw = (const uint32_t*)hbuf;
    #pragma unroll
    for (int i = 0; i < 2; i++) {
        int idx = tid + i*NTHR;
        int m = idx >> 3, q = idx & 7;
        uint4 w;
        int bw = m*33 + q*4;
        w.x = hw[bw]; w.y = hw[bw+1]; w.z = hw[bw+2]; w.w = hw[bw+3];
        *(uint4*)&hout[(size_t)(m0+m)*HID + ub + q*8] = w;
    }
    pdl_trigger();
}

// ---------------- merged encode step: phase A = layer1(t), phase B = layer0(t+1) ----------------
__global__ __launch_bounds__(NTHR, 1) void lstm_merged(
    const float* __restrict__ xf, int sx,            // x(t+1)
    const __half* __restrict__ h0in, const __half* __restrict__ h1in,
    __half* __restrict__ h1out, __half* __restrict__ h0out,
    float* __restrict__ c0glob, float* __restrict__ c1glob,
    int trig)
{
    extern __shared__ __align__(16) char smem[];
    const int tid = threadIdx.x, lane = tid & 31, wid = tid >> 5;
    const int m0 = blockIdx.x * 128, n0 = blockIdx.y * 256;
    const int wm0 = (wid >> 3) * 64, wn0 = (wid & 7) * 32;
    const int g = lane >> 2, tq = lane & 3;
    const uint32_t sbase = smem_u32(smem);
    float* bsm1 = (float*)smem;
    float* bsm0 = (float*)(smem + 1024);
    __half* HB2 = (__half*)(smem + OHB2);
    const int ub = n0 >> 2;
    const size_t cslot = (((size_t)blockIdx.x*2 + blockIdx.y)*NTHR + tid)*16;

    // ---- pre-wait: WB1, x(t+1), biases (all >=2-back or static) ----
    float xreg[8];
    if ((tid & 3) == 0) {
        int m = tid >> 2;
        *(float4*)&xreg[0] = __ldg((const float4*)(xf + (size_t)(m0+m)*sx));
        *(float4*)&xreg[4] = __ldg((const float4*)(xf + (size_t)(m0+m)*sx + 4));
    }
    {
        const int brow = tid >> 1, bq = tid & 1;
        #pragma unroll
        for (int j = 0; j < 8; j++) {
            cpa16(sbase + OB + (uint32_t)(brow*MBSTB + j*64 + bq*32),
                  (const char*)g_WB1 + ((size_t)(n0+brow)*KROW1 + j*32)*2 + bq*32);
            cpa16(sbase + OB + (uint32_t)(brow*MBSTB + j*64 + bq*32 + 16),
                  (const char*)g_WB1 + ((size_t)(n0+brow)*KROW1 + j*32)*2 + bq*32 + 16);
        }
    }
    if (tid < 256) { bsm1[tid] = g_b1[n0 + tid]; bsm0[tid] = g_b0[n0 + tid]; }

    // ---- wait, then 1-back loads: c1, A = [h0(t) | h1(t-1)] ----
    pdl_wait();

    float creg[16];
    {
        const float4* cp4 = (const float4*)(c1glob + cslot);
        #pragma unroll
        for (int i = 0; i < 4; i++) *(float4*)&creg[i*4] = __ldg(cp4 + i);
    }
    {
        const int arow = tid >> 2, aq = tid & 3;
        #pragma unroll
        for (int j = 0; j < 4; j++)
            cpa16(sbase + OA + (uint32_t)(arow*MASTB + j*64 + aq*16),
                  (const char*)(h0in + (size_t)(m0+arow)*HID + j*32) + aq*16);
        #pragma unroll
        for (int j = 4; j < 8; j++)
            cpa16(sbase + OA + (uint32_t)(arow*MASTB + j*64 + aq*16),
                  (const char*)(h1in + (size_t)(m0+arow)*HID + (j-4)*32) + aq*16);
    }
    CP_COMMIT();

    float acc[4][4][4];
    #pragma unroll
    for (int a = 0; a < 4; a++)
        #pragma unroll
        for (int b = 0; b < 4; b++)
            #pragma unroll
            for (int d = 0; d < 4; d++) acc[a][b][d] = 0.f;

    CP_WAIT0();
    __syncthreads();
    const int t4 = lane >> 3;
    const uint32_t a_base = sbase + OA
        + (uint32_t)((wm0 + (t4&1)*8 + (lane&7))*MASTB + ((t4>>1)*8)*2);
    const uint32_t b_base = sbase + OB
        + (uint32_t)((wn0 + (t4>>1)*8 + (lane&7))*MBSTB + ((t4&1)*8)*2);
    gemm_loop<8>(a_base, b_base, MASTB, MBSTB, acc);
    __syncthreads();    // phase-A reads of A done

    // ---- overlap: WB0 fill + x-chunk into A halves 128..159 ----
    {
        const int brow = tid >> 1, bq = tid & 1;
        #pragma unroll
        for (int j = 0; j < 5; j++) {
            cpa16(sbase + OB + (uint32_t)(brow*MBSTB + j*64 + bq*32),
                  (const char*)g_WB0 + ((size_t)(n0+brow)*KROW0 + j*32)*2 + bq*32);
            cpa16(sbase + OB + (uint32_t)(brow*MBSTB + j*64 + bq*32 + 16),
                  (const char*)g_WB0 + ((size_t)(n0+brow)*KROW0 + j*32)*2 + bq*32 + 16);
        }
        __half* Ah = (__half*)(smem + OA);
        int m = tid >> 2, part = tid & 3;
        if (part == 0) {
            __half hv[8];
            #pragma unroll
            for (int c = 0; c < 8; c++) hv[c] = __float2half_rn(xreg[c]);
            *(uint4*)&Ah[m*264 + 128] = *(uint4*)hv;
        } else {
            uint4 z = {0,0,0,0};
            *(uint4*)&Ah[m*264 + 128 + part*8] = z;
        }
    }
    CP_COMMIT();

    // ---- phase-A epilogue: c1 update, h1 -> HB2, c1 writeback, c0 load ----
    lstm_epilogue(acc, creg, bsm1, HB2, 66, wm0, wn0, g, tq, lane);
    {
        float4* cp4 = (float4*)(c1glob + cslot);
        #pragma unroll
        for (int i = 0; i < 4; i++) cp4[i] = *(float4*)&creg[i*4];
    }
    {
        const float4* cp4 = (const float4*)(c0glob + cslot);
        #pragma unroll
        for (int i = 0; i < 4; i++) *(float4*)&creg[i*4] = __ldg(cp4 + i);
    }
    __syncthreads();
    {   // h1(t) writeback
        const uint32_t* hw = (const uint32_t*)HB2;
        #pragma unroll
        for (int i = 0; i < 2; i++) {
            int idx = tid + i*NTHR;
            int m = idx >> 3, q = idx & 7;
            uint4 w;
            int bw = m*33 + q*4;
            w.x = hw[bw]; w.y = hw[bw+1]; w.z = hw[bw+2]; w.w = hw[bw+3];
            *(uint4*)&h1out[(size_t)(m0+m)*HID + ub + q*8] = w;
        }
    }

    // ---- phase B: layer0(t+1), A reused in place ----
    #pragma unroll
    for (int a = 0; a < 4; a++)
        #pragma unroll
        for (int b = 0; b < 4; b++)
            #pragma unroll
            for (int d = 0; d < 4; d++) acc[a][b][d] = 0.f;
    CP_WAIT0();
    __syncthreads();
    gemm_loop<5>(a_base, b_base, MASTB, MBSTB, acc);
    __syncthreads();

    lstm_epilogue(acc, creg, bsm0, HB2, 66, wm0, wn0, g, tq, lane);
    {
        float4* cp4 = (float4*)(c0glob + cslot);
        #pragma unroll
        for (int i = 0; i < 4; i++) cp4[i] = *(float4*)&creg[i*4];
    }
    __syncthreads();
    {   // h0(t+1) writeback
        const uint32_t* hw = (const uint32_t*)HB2;
        #pragma unroll
        for (int i = 0; i < 2; i++) {
            int idx = tid + i*NTHR;
            int m = idx >> 3, q = idx & 7;
            uint4 w;
            int bw = m*33 + q*4;
            w.x = hw[bw]; w.y = hw[bw+1]; w.z = hw[bw+2]; w.w = hw[bw+3];
            *(uint4*)&h0out[(size_t)(m0+m)*HID + ub + q*8] = w;
        }
    }
    if (trig) pdl_trigger();
}

// ---------------- tail: last horizon column ----------------
__global__ void fc_tail(const float* __restrict__ fcp, const float* __restrict__ bfc,
                        float* __restrict__ out)
{
    int row = blockIdx.x*128 + threadIdx.x;
    out[(size_t)row*HORIZON + (HORIZON-1)] = bfc[0] + fcp[row] + fcp[BATCH + row];
}

// ---------------- launch ----------------
extern "C" void kernel_launch(void* const* d_in, const int* in_sizes, int n_in,
                              void* d_out, int out_size)
{
    const float* inputs = (const float*)d_in[0];
    const float* Wih0 = (const float*)d_in[1];
    const float* Whh0 = (const float*)d_in[2];
    const float* bih0 = (const float*)d_in[3];
    const float* bhh0 = (const float*)d_in[4];
    const float* Wih1 = (const float*)d_in[5];
    const float* Whh1 = (const float*)d_in[6];
    const float* bih1 = (const float*)d_in[7];
    const float* bhh1 = (const float*)d_in[8];
    const float* Wfc  = (const float*)d_in[9];
    const float* bfc  = (const float*)d_in[10];
    float* out = (float*)d_out;

    __half *pWB0,*pWB1,*ph0,*ph1;
    float *pb0,*pb1,*pc0,*pc1,*pfcp;
    cudaGetSymbolAddress((void**)&pWB0, g_WB0);
    cudaGetSymbolAddress((void**)&pWB1, g_WB1);
    cudaGetSymbolAddress((void**)&pb0 , g_b0 );
    cudaGetSymbolAddress((void**)&pb1 , g_b1 );
    cudaGetSymbolAddress((void**)&ph0 , g_h0 );
    cudaGetSymbolAddress((void**)&ph1 , g_h1 );
    cudaGetSymbolAddress((void**)&pc0 , g_c0 );
    cudaGetSymbolAddress((void**)&pc1 , g_c1 );
    cudaGetSymbolAddress((void**)&pfcp, g_fcp);

    auto k0 = lstm_cell<KROW0/32, KROW0+8, KROW0+8, true >;
    auto k1 = lstm_cell<KROW1/32, KROW1+8, KROW1+8, false>;
    cudaFuncSetAttribute(k0, cudaFuncAttributeMaxDynamicSharedMemorySize, SMEM_STD);
    cudaFuncSetAttribute(k1, cudaFuncAttributeMaxDynamicSharedMemorySize, SMEM_STD);
    cudaFuncSetAttribute(lstm_merged, cudaFuncAttributeMaxDynamicSharedMemorySize, SMEM_MRG);

    prep_kernel<<<2048, 256>>>(Wih0, Whh0, bih0, bhh0, Wih1, Whh1, bih1, bhh1);

    dim3 grid(BATCH/128, 2);
    cudaLaunchConfig_t cfg = {};
    cfg.gridDim = grid;
    cfg.blockDim = dim3(NTHR, 1, 1);
    cfg.stream = 0;
    cudaLaunchAttribute attrs[1];
    attrs[0].id = cudaLaunchAttributeProgrammaticStreamSerialization;
    attrs[0].val.programmaticStreamSerializationAllowed = 1;
    cfg.attrs = attrs;
    cfg.numAttrs = 1;

    int b0 = 0, b1 = 0;
    // t=0: k0 standalone (h0_prev = zeros)
    cfg.dynamicSmemBytes = SMEM_STD;
    cudaLaunchKernelEx(&cfg, k0,
        (const float*)(inputs + 0*DIN), (int)(TSTEPS*DIN),
        (const __half*)(ph0 + b0*STATE), (const __half*)(ph0 + b0*STATE),
        (const __half*)pWB0, (const float*)pb0,
        pc0, (__half*)(ph0 + (1-b0)*STATE),
        Wfc, bfc, pfcp, out, 0, 0, 0);
    b0 ^= 1;
    // merged encode steps t = 0..47: phase A = L1(t), phase B = L0(t+1)
    cfg.dynamicSmemBytes = SMEM_MRG;
    for (int t = 0; t < 48; t++) {
        cudaLaunchKernelEx(&cfg, lstm_merged,
            (const float*)(inputs + (t+1)*DIN), (int)(TSTEPS*DIN),
            (const __half*)(ph0 + b0*STATE), (const __half*)(ph1 + b1*STATE),
            (__half*)(ph1 + (1-b1)*STATE), (__half*)(ph0 + (1-b0)*STATE),
            pc0, pc1,
            (t < 47) ? 1 : 0);
        b0 ^= 1; b1 ^= 1;
    }
    // k1(48): dofc
    cfg.dynamicSmemBytes = SMEM_STD;
    cudaLaunchKernelEx(&cfg, k1,
        (const float*)nullptr, 0,
        (const __half*)(ph0 + b0*STATE), (const __half*)(ph1 + b1*STATE),
        (const __half*)pWB1, (const float*)pb1,
        pc1, (__half*)(ph1 + (1-b1)*STATE),
        Wfc, bfc, pfcp, out, 0, 0, 1);
    b1 ^= 1;
    // decode t = 49..59: split k0/k1 as before
    for (int t = 49; t < TSTEPS; t++) {
        cudaLaunchKernelEx(&cfg, k0,
            (const float*)(inputs + t*DIN), (int)(TSTEPS*DIN),
            (const __half*)(ph0 + b0*STATE), (const __half*)(ph0 + b0*STATE),
            (const __half*)pWB0, (const float*)pb0,
            pc0, (__half*)(ph0 + (1-b0)*STATE),
            Wfc, bfc, pfcp, out, 1, t - 1 - LOOKBACK, 0);
        b0 ^= 1;
        cudaLaunchKernelEx(&cfg, k1,
            (const float*)nullptr, 0,
            (const __half*)(ph0 + b0*STATE), (const __half*)(ph1 + b1*STATE),
            (const __half*)pWB1, (const float*)pb1,
            pc1, (__half*)(ph1 + (1-b1)*STATE),
            Wfc, bfc, pfcp, out, 0, 0, 1);
        b1 ^= 1;
    }
    fc_tail<<<BATCH/128, 128>>>(pfcp, bfc, out);
}